// round 15
// baseline (speedup 1.0000x reference)
#include <cuda_runtime.h>
#include <cuda_fp16.h>
#include <cstdint>

// ---------------- static config ----------------
#define BB    16
#define HH    56
#define WW    56
#define CC    512
#define WSZ   7
#define SHIFT 3
#define NHEAD 16
#define HDIM  32
#define NTOK  49
#define NWIN_PER_B 64
#define NWIN  (BB*NWIN_PER_B)        // 1024
#define MROWS (NWIN*NTOK)            // 50176
#define SCALE 0.17677669529663687f
#define LNEPS 1e-5f

// ---------------- scratch (fp16 intermediates) ----------------
__device__ __half g_xw[(size_t)MROWS * CC];
__device__ __half g_yw[(size_t)MROWS * CC];
__device__ __half g_q [(size_t)MROWS * CC];
__device__ __half g_k [(size_t)MROWS * CC];
__device__ __half g_v [(size_t)MROWS * CC];
__device__ __half g_att[(size_t)MROWS * CC];
__device__ __half g_wt[4 * 512 * 512];       // pre-transposed weights [n][k], fp16
__device__ float  g_rpbT[NHEAD * 172];       // transposed rpb table [head][idx]

struct GemmArgs {
    const __half* A;
    const __half* W;
    const float*  bias;
    float         scale;
    void*         out;
    int           mode;   // 0: fp16 (win,head,n,d) scatter; 1: fp32 window-reverse
};

__device__ __forceinline__ uint32_t packh2(float a, float b) {
    __half2 h = __floats2half2_rn(a, b);
    return *(uint32_t*)&h;
}
__device__ __forceinline__ void mma_f16(float* c, const uint32_t* a, const uint32_t* b) {
    asm volatile("mma.sync.aligned.m16n8k16.row.col.f32.f16.f16.f32 "
        "{%0,%1,%2,%3}, {%4,%5,%6,%7}, {%8,%9}, {%0,%1,%2,%3};"
        : "+f"(c[0]), "+f"(c[1]), "+f"(c[2]), "+f"(c[3])
        : "r"(a[0]), "r"(a[1]), "r"(a[2]), "r"(a[3]), "r"(b[0]), "r"(b[1]));
}
__device__ __forceinline__ uint32_t smem_u32(const void* p) {
    uint32_t a;
    asm("{ .reg .u64 t; cvta.to.shared.u64 t, %1; cvt.u32.u64 %0, t; }" : "=r"(a) : "l"(p));
    return a;
}
#define LDSM4(r, addr) \
    asm volatile("ldmatrix.sync.aligned.m8n8.x4.shared.b16 {%0,%1,%2,%3}, [%4];" \
        : "=r"((r)[0]), "=r"((r)[1]), "=r"((r)[2]), "=r"((r)[3]) : "r"(addr))
#define LDSM4T(r, addr) \
    asm volatile("ldmatrix.sync.aligned.m8n8.x4.trans.shared.b16 {%0,%1,%2,%3}, [%4];" \
        : "=r"((r)[0]), "=r"((r)[1]), "=r"((r)[2]), "=r"((r)[3]) : "r"(addr))
#define CP16(sa, gp) \
    asm volatile("cp.async.cg.shared.global [%0], [%1], 16;" :: "r"(sa), "l"(gp))
#define CP_COMMIT() asm volatile("cp.async.commit_group;" ::: "memory")

// ================= Kernel 1: LayerNorm + roll(-3,-3) + window partition -> fp16 ==========
__global__ __launch_bounds__(256)
void ln_shift_window(const float* __restrict__ xa, const float* __restrict__ xb,
                     const float* __restrict__ ga, const float* __restrict__ ba,
                     const float* __restrict__ gb, const float* __restrict__ bb) {
    const int sel  = blockIdx.y;
    const int warp = threadIdx.x >> 5;
    const int lane = threadIdx.x & 31;
    const int pix  = blockIdx.x * 8 + warp;

    const float* __restrict__ x  = sel ? xb : xa;
    const float* __restrict__ g  = sel ? gb : ga;
    const float* __restrict__ be = sel ? bb : ba;
    __half* __restrict__ out     = sel ? g_yw : g_xw;

    const float4* __restrict__ xr = (const float4*)(x + (size_t)pix * CC);
    float4 v[4];
    #pragma unroll
    for (int j = 0; j < 4; j++) v[j] = xr[j * 32 + lane];

    float s = 0.0f, sq = 0.0f;
    #pragma unroll
    for (int j = 0; j < 4; j++) {
        s  += v[j].x + v[j].y + v[j].z + v[j].w;
        sq += v[j].x*v[j].x + v[j].y*v[j].y + v[j].z*v[j].z + v[j].w*v[j].w;
    }
    #pragma unroll
    for (int o = 16; o > 0; o >>= 1) {
        s  += __shfl_xor_sync(0xffffffffu, s,  o);
        sq += __shfl_xor_sync(0xffffffffu, sq, o);
    }

    const float mean = s * (1.0f / CC);
    const float var  = sq * (1.0f / CC) - mean * mean;
    const float inv  = rsqrtf(var + LNEPS);

    const int b   = pix / (HH * WW);
    const int rem = pix % (HH * WW);
    const int h   = rem / WW, w = rem % WW;
    int hr = h - SHIFT; if (hr < 0) hr += HH;
    int wr = w - SHIFT; if (wr < 0) wr += WW;
    const int win = b * NWIN_PER_B + (hr / WSZ) * 8 + (wr / WSZ);
    const int n   = (hr % WSZ) * WSZ + (wr % WSZ);
    uint32_t* orow = (uint32_t*)(out + ((size_t)(win * NTOK + n)) * CC);

    #pragma unroll
    for (int j = 0; j < 4; j++) {
        const float4 gg = ((const float4*)g)[j * 32 + lane];
        const float4 bt = ((const float4*)be)[j * 32 + lane];
        const float ox = (v[j].x - mean) * inv * gg.x + bt.x;
        const float oy = (v[j].y - mean) * inv * gg.y + bt.y;
        const float oz = (v[j].z - mean) * inv * gg.z + bt.z;
        const float ow = (v[j].w - mean) * inv * gg.w + bt.w;
        orow[(j * 32 + lane) * 2]     = packh2(ox, oy);
        orow[(j * 32 + lane) * 2 + 1] = packh2(oz, ow);
    }
}

// ================= Kernel 2: weight transpose (W[k][n] -> WT[n][k]) -> fp16 ==============
__global__ void transpose_w(const float* __restrict__ Wqa, const float* __restrict__ Wqb,
                            const float* __restrict__ Wp) {
    __shared__ float tile[32][33];
    const int m = blockIdx.z;
    const float* src; int ld, off;
    if      (m == 0) { src = Wqb; ld = 1536; off = 0;    }
    else if (m == 1) { src = Wqa; ld = 1536; off = 512;  }
    else if (m == 2) { src = Wqa; ld = 1536; off = 1024; }
    else             { src = Wp;  ld = 512;  off = 0;    }
    __half* dst = g_wt + (size_t)m * 512 * 512;
    const int n0 = blockIdx.x * 32, k0 = blockIdx.y * 32;
    const int tx = threadIdx.x, ty = threadIdx.y;
    #pragma unroll
    for (int i = 0; i < 32; i += 8)
        tile[ty + i][tx] = src[(size_t)(k0 + ty + i) * ld + off + n0 + tx];
    __syncthreads();
    #pragma unroll
    for (int i = 0; i < 32; i += 8)
        dst[(size_t)(n0 + ty + i) * 512 + k0 + tx] = __float2half_rn(tile[tx][ty + i]);
}

// ================= Kernel 2b: rpb transpose (169,16) -> (16,172) =================
__global__ void rpb_transpose(const float* __restrict__ rpb) {
    const int e = blockIdx.x * 256 + threadIdx.x;
    if (e < 169 * NHEAD) {
        const int h = e / 169, idx = e % 169;
        g_rpbT[h * 172 + idx] = rpb[idx * NHEAD + h];
    }
}

// ================= Kernel 3: fp16 mma.sync GEMM, 5-stage cp.async (R12/R14 config) =======
#define ROW_B  80
#define STG_B  (128 * ROW_B)                   // 10240
#define NSTG   5
#define SMEM_DYN (NSTG * 2 * STG_B)            // 102400

__global__ __launch_bounds__(256, 2)
void gemm_tc(GemmArgs g0, GemmArgs g1, GemmArgs g2) {
    extern __shared__ uint32_t smem[];

    const GemmArgs ga = (blockIdx.z == 0) ? g0 : ((blockIdx.z == 1) ? g1 : g2);

    const int bm   = blockIdx.y * 128;
    const int bn   = blockIdx.x * 128;
    const int t    = threadIdx.x;
    const int wid  = t >> 5;
    const int lane = t & 31;
    const int gid  = lane >> 2;
    const int tig  = lane & 3;
    const int wm   = wid & 3;
    const int wn   = wid >> 2;

    const uint32_t sBase = smem_u32(smem);
    const uint32_t bBase = sBase + NSTG * STG_B;

    const int r  = t >> 1;
    const int ch = t & 1;
    const __half* __restrict__ Ap = ga.A + (size_t)(bm + r) * 512 + ch * 16;
    const __half* __restrict__ Bp = ga.W + (size_t)(bn + r) * 512 + ch * 16;
    const uint32_t stsByte = (uint32_t)(r * ROW_B + ch * 32);

    #define PREFETCH(kt, st) do { \
        const uint32_t aDst = sBase + (st) * STG_B + stsByte; \
        const uint32_t bDst = bBase + (st) * STG_B + stsByte; \
        const __half* Aq = Ap + (kt) * 32; \
        const __half* Bq = Bp + (kt) * 32; \
        CP16(aDst,      Aq);     CP16(aDst + 16, Aq + 8); \
        CP16(bDst,      Bq);     CP16(bDst + 16, Bq + 8); \
        CP_COMMIT(); } while (0)

    const int mat  = lane >> 3;
    const int rInM = lane & 7;
    const uint32_t aOffL = (uint32_t)((wm * 32 + rInM + (mat & 1) * 8) * ROW_B
                                      + (mat >> 1) * 16);
    const uint32_t bOffL = (uint32_t)((wn * 64 + rInM + (mat & 1) * 8) * ROW_B
                                      + (mat >> 1) * 16);

    float acc[2][8][4];
    #pragma unroll
    for (int i = 0; i < 2; i++)
        #pragma unroll
        for (int j = 0; j < 8; j++)
            #pragma unroll
            for (int q = 0; q < 4; q++) acc[i][j][q] = 0.0f;

    PREFETCH(0, 0);
    PREFETCH(1, 1);
    PREFETCH(2, 2);

    #pragma unroll
    for (int kt = 0; kt < 16; ++kt) {
        if ((kt & 1) == 0) {
            if (kt <= 12) asm volatile("cp.async.wait_group 1;" ::: "memory");
            else          asm volatile("cp.async.wait_group 0;" ::: "memory");
            __syncthreads();
        }
        if (kt + 3 < 16) PREFETCH(kt + 3, (kt + 3) % NSTG);

        const int st = kt % NSTG;
        const uint32_t aB = sBase + st * STG_B + aOffL;
        const uint32_t bB = bBase + st * STG_B + bOffL;
        uint32_t aF[2][2][4], bF[2][4][4];
        #pragma unroll
        for (int ks = 0; ks < 2; ++ks) {
            LDSM4(aF[ks][0], aB + ks * 32);
            LDSM4(aF[ks][1], aB + 16 * ROW_B + ks * 32);
        }
        #pragma unroll
        for (int ks = 0; ks < 2; ++ks)
            #pragma unroll
            for (int jp = 0; jp < 4; ++jp)
                LDSM4(bF[ks][jp], bB + jp * 16 * ROW_B + ks * 32);
        #pragma unroll
        for (int ks = 0; ks < 2; ++ks)
            #pragma unroll
            for (int jp = 0; jp < 4; ++jp) {
                uint32_t b0[2] = { bF[ks][jp][0], bF[ks][jp][2] };
                uint32_t b1[2] = { bF[ks][jp][1], bF[ks][jp][3] };
                mma_f16(acc[0][2*jp],     aF[ks][0], b0);
                mma_f16(acc[0][2*jp + 1], aF[ks][0], b1);
                mma_f16(acc[1][2*jp],     aF[ks][1], b0);
                mma_f16(acc[1][2*jp + 1], aF[ks][1], b1);
            }
    }
    #undef PREFETCH

    const int row0 = bm + wm * 32;
    const int cw0  = bn + wn * 64;
    #pragma unroll
    for (int i = 0; i < 2; i++) {
        #pragma unroll
        for (int half = 0; half < 2; half++) {
            const int row = row0 + i * 16 + gid + half * 8;
            const int win = row / NTOK;
            const int n   = row % NTOK;
            if (ga.mode == 0) {
                __half* rowbase = (__half*)ga.out + ((size_t)win * NHEAD * NTOK + n) * HDIM;
                #pragma unroll
                for (int j = 0; j < 8; j++) {
                    const int c = cw0 + j * 8 + tig * 2;
                    const float2 bs = *(const float2*)(ga.bias + c);
                    const float vx = (acc[i][j][half * 2 + 0] + bs.x) * ga.scale;
                    const float vy = (acc[i][j][half * 2 + 1] + bs.y) * ga.scale;
                    const int head = c >> 5, d = c & 31;
                    *(uint32_t*)(rowbase + (size_t)head * NTOK * HDIM + d) = packh2(vx, vy);
                }
            } else {
                const int b  = win >> 6;
                const int lw = win & 63;
                const int hr = (lw >> 3) * WSZ + n / WSZ;
                const int wr = (lw & 7)  * WSZ + n % WSZ;
                int h = hr + SHIFT; if (h >= HH) h -= HH;
                int w = wr + SHIFT; if (w >= WW) w -= WW;
                float* rowbase = (float*)ga.out + ((size_t)b * (HH * WW) + h * WW + w) * CC;
                #pragma unroll
                for (int j = 0; j < 8; j++) {
                    const int c = cw0 + j * 8 + tig * 2;
                    const float2 bs = *(const float2*)(ga.bias + c);
                    float2 v;
                    v.x = (acc[i][j][half * 2 + 0] + bs.x) * ga.scale;
                    v.y = (acc[i][j][half * 2 + 1] + bs.y) * ga.scale;
                    *(float2*)(rowbase + c) = v;
                }
            }
        }
    }
}

// ================= Kernel 4: fp16 attention, 2 units per 256-thread block =================
__global__ __launch_bounds__(256)
void attn_mma() {
    const int half2u = threadIdx.x >> 7;           // which unit within block
    const int t      = threadIdx.x & 127;
    const int unit   = blockIdx.x * 2 + half2u;
    const int win    = unit >> 4;
    const int head   = unit & 15;
    const int nw     = win & (NWIN_PER_B - 1);

    __shared__ uint32_t Qs[2][64][20];
    __shared__ uint32_t Ks[2][64][20];
    __shared__ uint32_t Vs[2][64][20];
    __shared__ float rpb_s[2][172];
    __shared__ int   rid_s[2][52];

    const int wid  = t >> 5;
    const int lane = t & 31;
    const int gid  = lane >> 2;
    const int tig  = lane & 3;
    const int r0   = wid * 16;
    const int mat  = lane >> 3;
    const int rInM = lane & 7;

    const uint4* __restrict__ q4 = (const uint4*)(g_q + (size_t)unit * NTOK * HDIM);
    const uint4* __restrict__ k4 = (const uint4*)(g_k + (size_t)unit * NTOK * HDIM);
    const uint4* __restrict__ v4 = (const uint4*)(g_v + (size_t)unit * NTOK * HDIM);
    const uint4 z4 = make_uint4(0, 0, 0, 0);

    for (int e = t; e < 256; e += 128) {
        const int n = e >> 2, c = e & 3;
        const bool ok = n < NTOK;
        *(uint4*)&Qs[half2u][n][c * 4] = ok ? q4[n * 4 + c] : z4;
        *(uint4*)&Ks[half2u][n][c * 4] = ok ? k4[n * 4 + c] : z4;
        *(uint4*)&Vs[half2u][n][c * 4] = ok ? v4[n * 4 + c] : z4;
    }
    for (int e = t; e < 169; e += 128) rpb_s[half2u][e] = g_rpbT[head * 172 + e];
    if (t < NTOK) {
        const int i = t / WSZ, j = t % WSZ;
        const int h = (nw >> 3) * WSZ + i;
        const int w = (nw & 7)  * WSZ + j;
        const int rh = (h < HH - WSZ) ? 0 : ((h < HH - SHIFT) ? 1 : 2);
        const int rw = (w < WW - WSZ) ? 0 : ((w < WW - SHIFT) ? 1 : 2);
        rid_s[half2u][t] = rh * 3 + rw;
    }
    __syncthreads();

    const uint32_t QsB = smem_u32(&Qs[half2u][0][0]);
    const uint32_t KsB = smem_u32(&Ks[half2u][0][0]);
    const uint32_t VsB = smem_u32(&Vs[half2u][0][0]);
    const uint32_t aQ = QsB + ((r0 + rInM + (mat & 1) * 8) * 20 + (mat >> 1) * 4) * 4;
    const uint32_t bK = KsB + ((rInM + (mat & 1) * 8) * 20 + (mat >> 1) * 4) * 4;
    const uint32_t bV = VsB + ((rInM + (mat & 1) * 8) * 20 + (mat >> 1) * 4) * 4;

    const int rowA = r0 + gid;
    const int rowB = r0 + gid + 8;

    // ---- QK^T ----
    float accs[8][4];
    #pragma unroll
    for (int j = 0; j < 8; j++)
        #pragma unroll
        for (int q = 0; q < 4; q++) accs[j][q] = 0.0f;

    #pragma unroll
    for (int ks = 0; ks < 2; ++ks) {
        uint32_t aq[4], bq[4][4];
        LDSM4(aq,    aQ + ks * 32);
        LDSM4(bq[0], bK + 0 * 16 * 80 + ks * 32);
        LDSM4(bq[1], bK + 1 * 16 * 80 + ks * 32);
        LDSM4(bq[2], bK + 2 * 16 * 80 + ks * 32);
        LDSM4(bq[3], bK + 3 * 16 * 80 + ks * 32);
        #pragma unroll
        for (int jp = 0; jp < 4; ++jp) {
            uint32_t b0[2] = { bq[jp][0], bq[jp][2] };
            uint32_t b1[2] = { bq[jp][1], bq[jp][3] };
            mma_f16(accs[2*jp],     aq, b0);
            mma_f16(accs[2*jp + 1], aq, b1);
        }
    }

    // ---- rpb + shift-mask ----
    #pragma unroll
    for (int nt = 0; nt < 8; nt++) {
        #pragma unroll
        for (int q = 0; q < 4; q++) {
            const int row = (q >= 2) ? rowB : rowA;
            const int col = nt * 8 + tig * 2 + (q & 1);
            if (col >= NTOK) {
                accs[nt][q] = -1e30f;
            } else if (row < NTOK) {
                const int idx = (row / WSZ - col / WSZ + 6) * 13 + (row % WSZ - col % WSZ + 6);
                float a = accs[nt][q] + rpb_s[half2u][idx];
                if (rid_s[half2u][row] != rid_s[half2u][col]) a -= 100.0f;
                accs[nt][q] = a;
            }
        }
    }

    // ---- softmax ----
    float mx0 = -1e30f, mx1 = -1e30f;
    #pragma unroll
    for (int nt = 0; nt < 8; nt++) {
        mx0 = fmaxf(mx0, fmaxf(accs[nt][0], accs[nt][1]));
        mx1 = fmaxf(mx1, fmaxf(accs[nt][2], accs[nt][3]));
    }
    #pragma unroll
    for (int o = 1; o < 4; o <<= 1) {
        mx0 = fmaxf(mx0, __shfl_xor_sync(0xffffffffu, mx0, o));
        mx1 = fmaxf(mx1, __shfl_xor_sync(0xffffffffu, mx1, o));
    }
    float s0 = 0.0f, s1 = 0.0f;
    #pragma unroll
    for (int nt = 0; nt < 8; nt++) {
        float e0 = __expf(accs[nt][0] - mx0); accs[nt][0] = e0; s0 += e0;
        float e1 = __expf(accs[nt][1] - mx0); accs[nt][1] = e1; s0 += e1;
        float e2 = __expf(accs[nt][2] - mx1); accs[nt][2] = e2; s1 += e2;
        float e3 = __expf(accs[nt][3] - mx1); accs[nt][3] = e3; s1 += e3;
    }
    #pragma unroll
    for (int o = 1; o < 4; o <<= 1) {
        s0 += __shfl_xor_sync(0xffffffffu, s0, o);
        s1 += __shfl_xor_sync(0xffffffffu, s1, o);
    }
    const float i0 = 1.0f / s0, i1 = 1.0f / s1;

    // ---- PV: A-fragments built directly from QK accumulators ----
    float acco[4][4];
    #pragma unroll
    for (int j = 0; j < 4; j++)
        #pragma unroll
        for (int q = 0; q < 4; q++) acco[j][q] = 0.0f;

    #pragma unroll
    for (int ks = 0; ks < 4; ++ks) {
        uint32_t ap[4];
        ap[0] = packh2(accs[2*ks][0]     * i0, accs[2*ks][1]     * i0);
        ap[1] = packh2(accs[2*ks][2]     * i1, accs[2*ks][3]     * i1);
        ap[2] = packh2(accs[2*ks + 1][0] * i0, accs[2*ks + 1][1] * i0);
        ap[3] = packh2(accs[2*ks + 1][2] * i1, accs[2*ks + 1][3] * i1);
        uint32_t vq[2][4];
        LDSM4T(vq[0], bV + ks * 16 * 80);
        LDSM4T(vq[1], bV + ks * 16 * 80 + 32);
        #pragma unroll
        for (int dg = 0; dg < 2; ++dg) {
            uint32_t v0[2] = { vq[dg][0], vq[dg][1] };
            uint32_t v1[2] = { vq[dg][2], vq[dg][3] };
            mma_f16(acco[dg * 2],     ap, v0);
            mma_f16(acco[dg * 2 + 1], ap, v1);
        }
    }

    __half* __restrict__ ob = g_att + (size_t)win * NTOK * CC + head * HDIM;
    #pragma unroll
    for (int h = 0; h < 2; h++) {
        const int row = r0 + gid + h * 8;
        if (row < NTOK) {
            #pragma unroll
            for (int nt = 0; nt < 4; nt++) {
                const int d = nt * 8 + tig * 2;
                *(uint32_t*)(ob + (size_t)row * CC + d) = packh2(acco[nt][h * 2], acco[nt][h * 2 + 1]);
            }
        }
    }
}

// ================= launch =================
extern "C" void kernel_launch(void* const* d_in, const int* in_sizes, int n_in,
                              void* d_out, int out_size) {
    const float* rescaled = (const float*)d_in[0];
    const float* rescaler = (const float*)d_in[1];
    const float* gamma_a  = (const float*)d_in[2];
    const float* beta_a   = (const float*)d_in[3];
    const float* gamma_b  = (const float*)d_in[4];
    const float* beta_b   = (const float*)d_in[5];
    const float* Wqkv_a   = (const float*)d_in[6];
    const float* bqkv_a   = (const float*)d_in[7];
    const float* Wqkv_b   = (const float*)d_in[8];
    const float* bqkv_b   = (const float*)d_in[9];
    const float* rpb      = (const float*)d_in[10];
    const float* Wproj    = (const float*)d_in[11];
    const float* bproj    = (const float*)d_in[12];
    float* out = (float*)d_out;

    __half *p_xw, *p_yw, *p_q, *p_k, *p_v, *p_att, *p_wt;
    cudaGetSymbolAddress((void**)&p_xw,  g_xw);
    cudaGetSymbolAddress((void**)&p_yw,  g_yw);
    cudaGetSymbolAddress((void**)&p_q,   g_q);
    cudaGetSymbolAddress((void**)&p_k,   g_k);
    cudaGetSymbolAddress((void**)&p_v,   g_v);
    cudaGetSymbolAddress((void**)&p_att, g_att);
    cudaGetSymbolAddress((void**)&p_wt,  g_wt);

    cudaFuncSetAttribute(gemm_tc, cudaFuncAttributeMaxDynamicSharedMemorySize, SMEM_DYN);

    ln_shift_window<<<dim3(BB * HH * WW / 8, 2), 256>>>(rescaled, rescaler,
                                                        gamma_a, beta_a, gamma_b, beta_b);
    transpose_w<<<dim3(16, 16, 4), dim3(32, 8)>>>(Wqkv_a, Wqkv_b, Wproj);
    rpb_transpose<<<11, 256>>>(rpb);

    GemmArgs qa = { p_yw,  p_wt + 0 * 262144, bqkv_b,          SCALE, p_q,  0 };
    GemmArgs ka = { p_xw,  p_wt + 1 * 262144, bqkv_a + CC,     1.0f,  p_k,  0 };
    GemmArgs va = { p_xw,  p_wt + 2 * 262144, bqkv_a + 2*CC,   1.0f,  p_v,  0 };
    GemmArgs pa = { p_att, p_wt + 3 * 262144, bproj,           1.0f,  out,  1 };

    gemm_tc<<<dim3(4, MROWS / 128, 3), 256, SMEM_DYN>>>(qa, ka, va);

    attn_mma<<<NWIN * NHEAD / 2, 256>>>();

    gemm_tc<<<dim3(4, MROWS / 128, 1), 256, SMEM_DYN>>>(pa, pa, pa);
}

// round 16
// speedup vs baseline: 1.0239x; 1.0239x over previous
#include <cuda_runtime.h>
#include <cuda_fp16.h>
#include <cstdint>

// ---------------- static config ----------------
#define BB    16
#define HH    56
#define WW    56
#define CC    512
#define WSZ   7
#define SHIFT 3
#define NHEAD 16
#define HDIM  32
#define NTOK  49
#define NWIN_PER_B 64
#define NWIN  (BB*NWIN_PER_B)        // 1024
#define MROWS (NWIN*NTOK)            // 50176
#define SCALE 0.17677669529663687f
#define LNEPS 1e-5f

// ---------------- scratch (fp16 intermediates) ----------------
__device__ __half g_xw[(size_t)MROWS * CC];
__device__ __half g_yw[(size_t)MROWS * CC];
__device__ __half g_q [(size_t)MROWS * CC];
__device__ __half g_k [(size_t)MROWS * CC];
__device__ __half g_v [(size_t)MROWS * CC];
__device__ __half g_att[(size_t)MROWS * CC];
__device__ __half g_wt[4 * 512 * 512];       // pre-transposed weights [n][k], fp16
__device__ float  g_rpbT[NHEAD * 172];       // transposed rpb table [head][idx]

struct GemmArgs {
    const __half* A;
    const __half* W;
    const float*  bias;
    float         scale;
    void*         out;
    int           mode;   // 0: fp16 (win,head,n,d) scatter; 1: fp32 window-reverse
};

__device__ __forceinline__ uint32_t packh2(float a, float b) {
    __half2 h = __floats2half2_rn(a, b);
    return *(uint32_t*)&h;
}
__device__ __forceinline__ void mma_f16(float* c, const uint32_t* a, const uint32_t* b) {
    asm volatile("mma.sync.aligned.m16n8k16.row.col.f32.f16.f16.f32 "
        "{%0,%1,%2,%3}, {%4,%5,%6,%7}, {%8,%9}, {%0,%1,%2,%3};"
        : "+f"(c[0]), "+f"(c[1]), "+f"(c[2]), "+f"(c[3])
        : "r"(a[0]), "r"(a[1]), "r"(a[2]), "r"(a[3]), "r"(b[0]), "r"(b[1]));
}
__device__ __forceinline__ uint32_t smem_u32(const void* p) {
    uint32_t a;
    asm("{ .reg .u64 t; cvta.to.shared.u64 t, %1; cvt.u32.u64 %0, t; }" : "=r"(a) : "l"(p));
    return a;
}
#define LDSM4(r, addr) \
    asm volatile("ldmatrix.sync.aligned.m8n8.x4.shared.b16 {%0,%1,%2,%3}, [%4];" \
        : "=r"((r)[0]), "=r"((r)[1]), "=r"((r)[2]), "=r"((r)[3]) : "r"(addr))
#define LDSM4T(r, addr) \
    asm volatile("ldmatrix.sync.aligned.m8n8.x4.trans.shared.b16 {%0,%1,%2,%3}, [%4];" \
        : "=r"((r)[0]), "=r"((r)[1]), "=r"((r)[2]), "=r"((r)[3]) : "r"(addr))
#define CP16(sa, gp) \
    asm volatile("cp.async.cg.shared.global [%0], [%1], 16;" :: "r"(sa), "l"(gp))
#define CP_COMMIT() asm volatile("cp.async.commit_group;" ::: "memory")

// ================= Kernel 1: fused prep =================
// bid [0,1568):        LN + roll + window partition (warp-per-pixel, 2 streams)
// bid [1568,2592):     weight transpose (4 slices x 256 tiles)
// bid [2592,2603):     rpb transpose
#define LN_BLKS   (BB * HH * WW / 8 * 2)   // 1568
#define TW_BLKS   1024
#define PREP_BLKS (LN_BLKS + TW_BLKS + 11)

__global__ __launch_bounds__(256)
void prep_kernel(const float* __restrict__ xa, const float* __restrict__ xb,
                 const float* __restrict__ ga, const float* __restrict__ ba,
                 const float* __restrict__ gb, const float* __restrict__ bb,
                 const float* __restrict__ Wqa, const float* __restrict__ Wqb,
                 const float* __restrict__ Wp,  const float* __restrict__ rpb) {
    __shared__ float tile[32][33];
    const int bid = blockIdx.x;

    if (bid < LN_BLKS) {
        // ---- LayerNorm + roll(-3,-3) + window partition ----
        const int sel  = bid >= (LN_BLKS / 2);
        const int blk  = sel ? bid - LN_BLKS / 2 : bid;
        const int warp = threadIdx.x >> 5;
        const int lane = threadIdx.x & 31;
        const int pix  = blk * 8 + warp;

        const float* __restrict__ x  = sel ? xb : xa;
        const float* __restrict__ g  = sel ? gb : ga;
        const float* __restrict__ be = sel ? bb : ba;
        __half* __restrict__ out     = sel ? g_yw : g_xw;

        const float4* __restrict__ xr = (const float4*)(x + (size_t)pix * CC);
        float4 v[4];
        #pragma unroll
        for (int j = 0; j < 4; j++) v[j] = xr[j * 32 + lane];

        float s = 0.0f, sq = 0.0f;
        #pragma unroll
        for (int j = 0; j < 4; j++) {
            s  += v[j].x + v[j].y + v[j].z + v[j].w;
            sq += v[j].x*v[j].x + v[j].y*v[j].y + v[j].z*v[j].z + v[j].w*v[j].w;
        }
        #pragma unroll
        for (int o = 16; o > 0; o >>= 1) {
            s  += __shfl_xor_sync(0xffffffffu, s,  o);
            sq += __shfl_xor_sync(0xffffffffu, sq, o);
        }

        const float mean = s * (1.0f / CC);
        const float var  = sq * (1.0f / CC) - mean * mean;
        const float inv  = rsqrtf(var + LNEPS);

        const int b   = pix / (HH * WW);
        const int rem = pix % (HH * WW);
        const int h   = rem / WW, w = rem % WW;
        int hr = h - SHIFT; if (hr < 0) hr += HH;
        int wr = w - SHIFT; if (wr < 0) wr += WW;
        const int win = b * NWIN_PER_B + (hr / WSZ) * 8 + (wr / WSZ);
        const int n   = (hr % WSZ) * WSZ + (wr % WSZ);
        uint32_t* orow = (uint32_t*)(out + ((size_t)(win * NTOK + n)) * CC);

        #pragma unroll
        for (int j = 0; j < 4; j++) {
            const float4 gg = ((const float4*)g)[j * 32 + lane];
            const float4 bt = ((const float4*)be)[j * 32 + lane];
            const float ox = (v[j].x - mean) * inv * gg.x + bt.x;
            const float oy = (v[j].y - mean) * inv * gg.y + bt.y;
            const float oz = (v[j].z - mean) * inv * gg.z + bt.z;
            const float ow = (v[j].w - mean) * inv * gg.w + bt.w;
            orow[(j * 32 + lane) * 2]     = packh2(ox, oy);
            orow[(j * 32 + lane) * 2 + 1] = packh2(oz, ow);
        }
    } else if (bid < LN_BLKS + TW_BLKS) {
        // ---- weight transpose W[k][n] -> WT[n][k] (fp16) ----
        const int idx = bid - LN_BLKS;
        const int m   = idx >> 8;           // 0..3
        const int rem = idx & 255;
        const int n0  = (rem & 15) * 32;
        const int k0  = (rem >> 4) * 32;
        const float* src; int ld, off;
        if      (m == 0) { src = Wqb; ld = 1536; off = 0;    }
        else if (m == 1) { src = Wqa; ld = 1536; off = 512;  }
        else if (m == 2) { src = Wqa; ld = 1536; off = 1024; }
        else             { src = Wp;  ld = 512;  off = 0;    }
        __half* dst = g_wt + (size_t)m * 512 * 512;
        const int tx = threadIdx.x & 31, ty = threadIdx.x >> 5;
        #pragma unroll
        for (int i = 0; i < 32; i += 8)
            tile[ty + i][tx] = src[(size_t)(k0 + ty + i) * ld + off + n0 + tx];
        __syncthreads();
        #pragma unroll
        for (int i = 0; i < 32; i += 8)
            dst[(size_t)(n0 + ty + i) * 512 + k0 + tx] = __float2half_rn(tile[tx][ty + i]);
    } else {
        // ---- rpb transpose (169,16) -> (16,172) ----
        const int e = (bid - LN_BLKS - TW_BLKS) * 256 + threadIdx.x;
        if (e < 169 * NHEAD) {
            const int h = e / 169, idx = e % 169;
            g_rpbT[h * 172 + idx] = rpb[idx * NHEAD + h];
        }
    }
}

// ================= Kernel 3: fp16 mma.sync GEMM, 5-stage cp.async (R12/R14 config) =======
#define ROW_B  80
#define STG_B  (128 * ROW_B)                   // 10240
#define NSTG   5
#define SMEM_DYN (NSTG * 2 * STG_B)            // 102400

__global__ __launch_bounds__(256, 2)
void gemm_tc(GemmArgs g0, GemmArgs g1, GemmArgs g2) {
    extern __shared__ uint32_t smem[];

    const GemmArgs ga = (blockIdx.z == 0) ? g0 : ((blockIdx.z == 1) ? g1 : g2);

    const int bm   = blockIdx.y * 128;
    const int bn   = blockIdx.x * 128;
    const int t    = threadIdx.x;
    const int wid  = t >> 5;
    const int lane = t & 31;
    const int gid  = lane >> 2;
    const int tig  = lane & 3;
    const int wm   = wid & 3;
    const int wn   = wid >> 2;

    const uint32_t sBase = smem_u32(smem);
    const uint32_t bBase = sBase + NSTG * STG_B;

    const int r  = t >> 1;
    const int ch = t & 1;
    const __half* __restrict__ Ap = ga.A + (size_t)(bm + r) * 512 + ch * 16;
    const __half* __restrict__ Bp = ga.W + (size_t)(bn + r) * 512 + ch * 16;
    const uint32_t stsByte = (uint32_t)(r * ROW_B + ch * 32);

    #define PREFETCH(kt, st) do { \
        const uint32_t aDst = sBase + (st) * STG_B + stsByte; \
        const uint32_t bDst = bBase + (st) * STG_B + stsByte; \
        const __half* Aq = Ap + (kt) * 32; \
        const __half* Bq = Bp + (kt) * 32; \
        CP16(aDst,      Aq);     CP16(aDst + 16, Aq + 8); \
        CP16(bDst,      Bq);     CP16(bDst + 16, Bq + 8); \
        CP_COMMIT(); } while (0)

    const int mat  = lane >> 3;
    const int rInM = lane & 7;
    const uint32_t aOffL = (uint32_t)((wm * 32 + rInM + (mat & 1) * 8) * ROW_B
                                      + (mat >> 1) * 16);
    const uint32_t bOffL = (uint32_t)((wn * 64 + rInM + (mat & 1) * 8) * ROW_B
                                      + (mat >> 1) * 16);

    float acc[2][8][4];
    #pragma unroll
    for (int i = 0; i < 2; i++)
        #pragma unroll
        for (int j = 0; j < 8; j++)
            #pragma unroll
            for (int q = 0; q < 4; q++) acc[i][j][q] = 0.0f;

    PREFETCH(0, 0);
    PREFETCH(1, 1);
    PREFETCH(2, 2);

    #pragma unroll
    for (int kt = 0; kt < 16; ++kt) {
        if ((kt & 1) == 0) {
            if (kt <= 12) asm volatile("cp.async.wait_group 1;" ::: "memory");
            else          asm volatile("cp.async.wait_group 0;" ::: "memory");
            __syncthreads();
        }
        if (kt + 3 < 16) PREFETCH(kt + 3, (kt + 3) % NSTG);

        const int st = kt % NSTG;
        const uint32_t aB = sBase + st * STG_B + aOffL;
        const uint32_t bB = bBase + st * STG_B + bOffL;
        uint32_t aF[2][2][4], bF[2][4][4];
        #pragma unroll
        for (int ks = 0; ks < 2; ++ks) {
            LDSM4(aF[ks][0], aB + ks * 32);
            LDSM4(aF[ks][1], aB + 16 * ROW_B + ks * 32);
        }
        #pragma unroll
        for (int ks = 0; ks < 2; ++ks)
            #pragma unroll
            for (int jp = 0; jp < 4; ++jp)
                LDSM4(bF[ks][jp], bB + jp * 16 * ROW_B + ks * 32);
        #pragma unroll
        for (int ks = 0; ks < 2; ++ks)
            #pragma unroll
            for (int jp = 0; jp < 4; ++jp) {
                uint32_t b0[2] = { bF[ks][jp][0], bF[ks][jp][2] };
                uint32_t b1[2] = { bF[ks][jp][1], bF[ks][jp][3] };
                mma_f16(acc[0][2*jp],     aF[ks][0], b0);
                mma_f16(acc[0][2*jp + 1], aF[ks][0], b1);
                mma_f16(acc[1][2*jp],     aF[ks][1], b0);
                mma_f16(acc[1][2*jp + 1], aF[ks][1], b1);
            }
    }
    #undef PREFETCH

    const int row0 = bm + wm * 32;
    const int cw0  = bn + wn * 64;
    #pragma unroll
    for (int i = 0; i < 2; i++) {
        #pragma unroll
        for (int half = 0; half < 2; half++) {
            const int row = row0 + i * 16 + gid + half * 8;
            const int win = row / NTOK;
            const int n   = row % NTOK;
            if (ga.mode == 0) {
                __half* rowbase = (__half*)ga.out + ((size_t)win * NHEAD * NTOK + n) * HDIM;
                #pragma unroll
                for (int j = 0; j < 8; j++) {
                    const int c = cw0 + j * 8 + tig * 2;
                    const float2 bs = *(const float2*)(ga.bias + c);
                    const float vx = (acc[i][j][half * 2 + 0] + bs.x) * ga.scale;
                    const float vy = (acc[i][j][half * 2 + 1] + bs.y) * ga.scale;
                    const int head = c >> 5, d = c & 31;
                    *(uint32_t*)(rowbase + (size_t)head * NTOK * HDIM + d) = packh2(vx, vy);
                }
            } else {
                const int b  = win >> 6;
                const int lw = win & 63;
                const int hr = (lw >> 3) * WSZ + n / WSZ;
                const int wr = (lw & 7)  * WSZ + n % WSZ;
                int h = hr + SHIFT; if (h >= HH) h -= HH;
                int w = wr + SHIFT; if (w >= WW) w -= WW;
                float* rowbase = (float*)ga.out + ((size_t)b * (HH * WW) + h * WW + w) * CC;
                #pragma unroll
                for (int j = 0; j < 8; j++) {
                    const int c = cw0 + j * 8 + tig * 2;
                    const float2 bs = *(const float2*)(ga.bias + c);
                    float2 v;
                    v.x = (acc[i][j][half * 2 + 0] + bs.x) * ga.scale;
                    v.y = (acc[i][j][half * 2 + 1] + bs.y) * ga.scale;
                    *(float2*)(rowbase + c) = v;
                }
            }
        }
    }
}

// ================= Kernel 4: fp16 attention, P in registers (R14 config) =================
__global__ __launch_bounds__(128)
void attn_mma() {
    const int unit = blockIdx.x;
    const int win  = unit >> 4;
    const int head = unit & 15;
    const int nw   = win & (NWIN_PER_B - 1);

    __shared__ uint32_t Qs[64][20];
    __shared__ uint32_t Ks[64][20];
    __shared__ uint32_t Vs[64][20];
    __shared__ float rpb_s[169];
    __shared__ int   rid_s[NTOK];

    const int t    = threadIdx.x;
    const int wid  = t >> 5;
    const int lane = t & 31;
    const int gid  = lane >> 2;
    const int tig  = lane & 3;
    const int r0   = wid * 16;
    const int mat  = lane >> 3;
    const int rInM = lane & 7;

    const uint4* __restrict__ q4 = (const uint4*)(g_q + (size_t)unit * NTOK * HDIM);
    const uint4* __restrict__ k4 = (const uint4*)(g_k + (size_t)unit * NTOK * HDIM);
    const uint4* __restrict__ v4 = (const uint4*)(g_v + (size_t)unit * NTOK * HDIM);
    const uint4 z4 = make_uint4(0, 0, 0, 0);

    for (int e = t; e < 256; e += 128) {
        const int n = e >> 2, c = e & 3;
        const bool ok = n < NTOK;
        *(uint4*)&Qs[n][c * 4] = ok ? q4[n * 4 + c] : z4;
        *(uint4*)&Ks[n][c * 4] = ok ? k4[n * 4 + c] : z4;
        *(uint4*)&Vs[n][c * 4] = ok ? v4[n * 4 + c] : z4;
    }
    for (int e = t; e < 169; e += 128) rpb_s[e] = g_rpbT[head * 172 + e];
    if (t < NTOK) {
        const int i = t / WSZ, j = t % WSZ;
        const int h = (nw >> 3) * WSZ + i;
        const int w = (nw & 7)  * WSZ + j;
        const int rh = (h < HH - WSZ) ? 0 : ((h < HH - SHIFT) ? 1 : 2);
        const int rw = (w < WW - WSZ) ? 0 : ((w < WW - SHIFT) ? 1 : 2);
        rid_s[t] = rh * 3 + rw;
    }
    __syncthreads();

    const uint32_t QsB = smem_u32(Qs), KsB = smem_u32(Ks), VsB = smem_u32(Vs);
    const uint32_t aQ = QsB + ((r0 + rInM + (mat & 1) * 8) * 20 + (mat >> 1) * 4) * 4;
    const uint32_t bK = KsB + ((rInM + (mat & 1) * 8) * 20 + (mat >> 1) * 4) * 4;
    const uint32_t bV = VsB + ((rInM + (mat & 1) * 8) * 20 + (mat >> 1) * 4) * 4;

    const int rowA = r0 + gid;
    const int rowB = r0 + gid + 8;

    float accs[8][4];
    #pragma unroll
    for (int j = 0; j < 8; j++)
        #pragma unroll
        for (int q = 0; q < 4; q++) accs[j][q] = 0.0f;

    #pragma unroll
    for (int ks = 0; ks < 2; ++ks) {
        uint32_t aq[4], bq[4][4];
        LDSM4(aq,    aQ + ks * 32);
        LDSM4(bq[0], bK + 0 * 16 * 80 + ks * 32);
        LDSM4(bq[1], bK + 1 * 16 * 80 + ks * 32);
        LDSM4(bq[2], bK + 2 * 16 * 80 + ks * 32);
        LDSM4(bq[3], bK + 3 * 16 * 80 + ks * 32);
        #pragma unroll
        for (int jp = 0; jp < 4; ++jp) {
            uint32_t b0[2] = { bq[jp][0], bq[jp][2] };
            uint32_t b1[2] = { bq[jp][1], bq[jp][3] };
            mma_f16(accs[2*jp],     aq, b0);
            mma_f16(accs[2*jp + 1], aq, b1);
        }
    }

    #pragma unroll
    for (int nt = 0; nt < 8; nt++) {
        #pragma unroll
        for (int q = 0; q < 4; q++) {
            const int row = (q >= 2) ? rowB : rowA;
            const int col = nt * 8 + tig * 2 + (q & 1);
            if (col >= NTOK) {
                accs[nt][q] = -1e30f;
            } else if (row < NTOK) {
                const int idx = (row / WSZ - col / WSZ + 6) * 13 + (row % WSZ - col % WSZ + 6);
                float a = accs[nt][q] + rpb_s[idx];
                if (rid_s[row] != rid_s[col]) a -= 100.0f;
                accs[nt][q] = a;
            }
        }
    }

    float mx0 = -1e30f, mx1 = -1e30f;
    #pragma unroll
    for (int nt = 0; nt < 8; nt++) {
        mx0 = fmaxf(mx0, fmaxf(accs[nt][0], accs[nt][1]));
        mx1 = fmaxf(mx1, fmaxf(accs[nt][2], accs[nt][3]));
    }
    #pragma unroll
    for (int o = 1; o < 4; o <<= 1) {
        mx0 = fmaxf(mx0, __shfl_xor_sync(0xffffffffu, mx0, o));
        mx1 = fmaxf(mx1, __shfl_xor_sync(0xffffffffu, mx1, o));
    }
    float s0 = 0.0f, s1 = 0.0f;
    #pragma unroll
    for (int nt = 0; nt < 8; nt++) {
        float e0 = __expf(accs[nt][0] - mx0); accs[nt][0] = e0; s0 += e0;
        float e1 = __expf(accs[nt][1] - mx0); accs[nt][1] = e1; s0 += e1;
        float e2 = __expf(accs[nt][2] - mx1); accs[nt][2] = e2; s1 += e2;
        float e3 = __expf(accs[nt][3] - mx1); accs[nt][3] = e3; s1 += e3;
    }
    #pragma unroll
    for (int o = 1; o < 4; o <<= 1) {
        s0 += __shfl_xor_sync(0xffffffffu, s0, o);
        s1 += __shfl_xor_sync(0xffffffffu, s1, o);
    }
    const float i0 = 1.0f / s0, i1 = 1.0f / s1;

    float acco[4][4];
    #pragma unroll
    for (int j = 0; j < 4; j++)
        #pragma unroll
        for (int q = 0; q < 4; q++) acco[j][q] = 0.0f;

    #pragma unroll
    for (int ks = 0; ks < 4; ++ks) {
        uint32_t ap[4];
        ap[0] = packh2(accs[2*ks][0]     * i0, accs[2*ks][1]     * i0);
        ap[1] = packh2(accs[2*ks][2]     * i1, accs[2*ks][3]     * i1);
        ap[2] = packh2(accs[2*ks + 1][0] * i0, accs[2*ks + 1][1] * i0);
        ap[3] = packh2(accs[2*ks + 1][2] * i1, accs[2*ks + 1][3] * i1);
        uint32_t vq[2][4];
        LDSM4T(vq[0], bV + ks * 16 * 80);
        LDSM4T(vq[1], bV + ks * 16 * 80 + 32);
        #pragma unroll
        for (int dg = 0; dg < 2; ++dg) {
            uint32_t v0[2] = { vq[dg][0], vq[dg][1] };
            uint32_t v1[2] = { vq[dg][2], vq[dg][3] };
            mma_f16(acco[dg * 2],     ap, v0);
            mma_f16(acco[dg * 2 + 1], ap, v1);
        }
    }

    __half* __restrict__ ob = g_att + (size_t)win * NTOK * CC + head * HDIM;
    #pragma unroll
    for (int h = 0; h < 2; h++) {
        const int row = r0 + gid + h * 8;
        if (row < NTOK) {
            #pragma unroll
            for (int nt = 0; nt < 4; nt++) {
                const int d = nt * 8 + tig * 2;
                *(uint32_t*)(ob + (size_t)row * CC + d) = packh2(acco[nt][h * 2], acco[nt][h * 2 + 1]);
            }
        }
    }
}

// ================= launch =================
extern "C" void kernel_launch(void* const* d_in, const int* in_sizes, int n_in,
                              void* d_out, int out_size) {
    const float* rescaled = (const float*)d_in[0];
    const float* rescaler = (const float*)d_in[1];
    const float* gamma_a  = (const float*)d_in[2];
    const float* beta_a   = (const float*)d_in[3];
    const float* gamma_b  = (const float*)d_in[4];
    const float* beta_b   = (const float*)d_in[5];
    const float* Wqkv_a   = (const float*)d_in[6];
    const float* bqkv_a   = (const float*)d_in[7];
    const float* Wqkv_b   = (const float*)d_in[8];
    const float* bqkv_b   = (const float*)d_in[9];
    const float* rpb      = (const float*)d_in[10];
    const float* Wproj    = (const float*)d_in[11];
    const float* bproj    = (const float*)d_in[12];
    float* out = (float*)d_out;

    __half *p_xw, *p_yw, *p_q, *p_k, *p_v, *p_att, *p_wt;
    cudaGetSymbolAddress((void**)&p_xw,  g_xw);
    cudaGetSymbolAddress((void**)&p_yw,  g_yw);
    cudaGetSymbolAddress((void**)&p_q,   g_q);
    cudaGetSymbolAddress((void**)&p_k,   g_k);
    cudaGetSymbolAddress((void**)&p_v,   g_v);
    cudaGetSymbolAddress((void**)&p_att, g_att);
    cudaGetSymbolAddress((void**)&p_wt,  g_wt);

    cudaFuncSetAttribute(gemm_tc, cudaFuncAttributeMaxDynamicSharedMemorySize, SMEM_DYN);

    // fused prep: LN (both streams) + weight transpose + rpb transpose
    prep_kernel<<<PREP_BLKS, 256>>>(rescaled, rescaler, gamma_a, beta_a, gamma_b, beta_b,
                                    Wqkv_a, Wqkv_b, Wproj, rpb);

    GemmArgs qa = { p_yw,  p_wt + 0 * 262144, bqkv_b,          SCALE, p_q,  0 };
    GemmArgs ka = { p_xw,  p_wt + 1 * 262144, bqkv_a + CC,     1.0f,  p_k,  0 };
    GemmArgs va = { p_xw,  p_wt + 2 * 262144, bqkv_a + 2*CC,   1.0f,  p_v,  0 };
    GemmArgs pa = { p_att, p_wt + 3 * 262144, bproj,           1.0f,  out,  1 };

    gemm_tc<<<dim3(4, MROWS / 128, 3), 256, SMEM_DYN>>>(qa, ka, va);

    attn_mma<<<NWIN * NHEAD, 128>>>();

    gemm_tc<<<dim3(4, MROWS / 128, 1), 256, SMEM_DYN>>>(pa, pa, pa);
}